// round 7
// baseline (speedup 1.0000x reference)
#include <cuda_runtime.h>
#include <cstdint>

#define NB   32
#define NH   128
#define RS   44        // h row stride (floats): [0,4) L-halo | [4,36/37) owned | R-halo | pad
#define NITER 131
#define NTHREADS 512

// hs: channel c at c*RS + (c>=64 ? 16 : 0)          -> 128*44+16 = 5648 floats
#define HS_CH1    2832         // 64*44 + 16
#define HS_FLOATS 5648
// ws: ws[(c*3+k)*128 + o] + (c>=64 ? 16 : 0)        -> 128*384+16 = 49168 floats
#define WS_CH1    24592        // 64*384 + 16
#define WS_FLOATS 49168

typedef unsigned long long u64t;

// ---------- packed f32x2 helpers ----------
__device__ __forceinline__ u64t pk2(float a, float b){
    u64t r; asm("mov.b64 %0, {%1, %2};" : "=l"(r) : "f"(a), "f"(b)); return r;
}
__device__ __forceinline__ void fma2(u64t& d, u64t a, u64t b){
    asm("fma.rn.f32x2 %0, %1, %2, %0;" : "+l"(d) : "l"(a), "l"(b));
}
__device__ __forceinline__ void unpk2(u64t v, float& a, float& b){
    asm("mov.b64 {%0, %1}, %2;" : "=f"(a), "=f"(b) : "l"(v));
}
__device__ __forceinline__ float lo2(u64t v){ float a,b; unpk2(v,a,b); return a; }
__device__ __forceinline__ float hi2(u64t v){ float a,b; unpk2(v,a,b); return b; }

__device__ __forceinline__ uint32_t mapa32(uint32_t addr, uint32_t rank){
    uint32_t r; asm("mapa.shared::cluster.u32 %0, %1, %2;" : "=r"(r) : "r"(addr), "r"(rank));
    return r;
}
__device__ __forceinline__ void st_cl_u64(uint32_t addr, u64t v){
    asm volatile("st.shared::cluster.b64 [%0], %1;" :: "r"(addr), "l"(v) : "memory");
}

#define CLUSTER_SYNC() do { \
    asm volatile("barrier.cluster.arrive.aligned;" ::: "memory"); \
    asm volatile("barrier.cluster.wait.aligned;"   ::: "memory"); } while(0)

// One residual dilated-conv iteration; h stays resident in smem.
// Lanes: og_lo=lane[0:3), ch=lane[3], ttlo=lane[4]. Warps: oghi=w[0:3), tthi=w[3].
// Thread tile: 2 out-ch x 8 t, summed over a 64-channel half; shfl.bfly(8) completes sum.
template<int D>
__device__ __forceinline__ void conv_iter(
    float* __restrict__ hs, const float* __restrict__ ws, const float* __restrict__ cb,
    uint32_t lP, uint32_t rP, int tg)
{
    const int tid  = threadIdx.x;
    const int lane = tid & 31;
    const int w    = tid >> 5;
    const int og   = ((w & 7) << 3) | (lane & 7);           // 0..63 (pair of out-ch)
    const int ch   = (lane >> 3) & 1;
    const int tt   = (((w >> 3) & 1) << 1) | ((lane >> 4) & 1);   // 0..3
    const bool sp  = (tg == 3) && (tt == 3);                // also produce t=128

    u64t acc[2][4] = {{0ull,0ull,0ull,0ull},{0ull,0ull,0ull,0ull}};
    float accx[2] = {0.f, 0.f};

    // window: 16 floats = local cols [tt*8, tt*8+16); owned outputs at window cols [4,12)
    const char*  hb = (const char*)(hs + ch*HS_CH1 + tt*8);
    const float* wb = ws + ch*WS_CH1 + og*2;

    #pragma unroll 2
    for (int cc = 0; cc < 64; cc++){
        ulonglong2 a0 = *(const ulonglong2*)(hb);
        ulonglong2 a1 = *(const ulonglong2*)(hb + 16);
        ulonglong2 a2 = *(const ulonglong2*)(hb + 32);
        ulonglong2 a3 = *(const ulonglong2*)(hb + 48);
        float2 w0 = *(const float2*)(wb);
        float2 w1 = *(const float2*)(wb + 128);
        float2 w2 = *(const float2*)(wb + 256);
        u64t u[8] = {a0.x, a0.y, a1.x, a1.y, a2.x, a2.y, a3.x, a3.y};

        if (D != 1){
            constexpr int S0 = (D == 4) ? 0 : 1;
            constexpr int S2 = (D == 4) ? 4 : 3;
            #define DOO(oi, v0, v1, v2) do {                                   \
                u64t d0 = pk2((v0),(v0)), d1 = pk2((v1),(v1)), d2 = pk2((v2),(v2)); \
                fma2(acc[oi][0], d0, u[S0+0]); fma2(acc[oi][1], d0, u[S0+1]);  \
                fma2(acc[oi][2], d0, u[S0+2]); fma2(acc[oi][3], d0, u[S0+3]);  \
                fma2(acc[oi][0], d1, u[2]);    fma2(acc[oi][1], d1, u[3]);     \
                fma2(acc[oi][2], d1, u[4]);    fma2(acc[oi][3], d1, u[5]);     \
                fma2(acc[oi][0], d2, u[S2+0]); fma2(acc[oi][1], d2, u[S2+1]);  \
                fma2(acc[oi][2], d2, u[S2+2]); fma2(acc[oi][3], d2, u[S2+3]);  \
            } while(0)
            DOO(0, w0.x, w1.x, w2.x);
            DOO(1, w0.y, w1.y, w2.y);
            #undef DOO
        } else {
            float s[16];
            #pragma unroll
            for (int j = 0; j < 8; j++) unpk2(u[j], s[2*j], s[2*j+1]);
            u64t om[6];
            #pragma unroll
            for (int j = 1; j < 6; j++) om[j] = pk2(s[2*j+1], s[2*j+2]);
            #define DOO1(oi, v0, v1, v2) do {                                  \
                u64t d0 = pk2((v0),(v0)), d1 = pk2((v1),(v1)), d2 = pk2((v2),(v2)); \
                fma2(acc[oi][0], d0, om[1]); fma2(acc[oi][1], d0, om[2]);      \
                fma2(acc[oi][2], d0, om[3]); fma2(acc[oi][3], d0, om[4]);      \
                fma2(acc[oi][0], d1, u[2]);  fma2(acc[oi][1], d1, u[3]);       \
                fma2(acc[oi][2], d1, u[4]);  fma2(acc[oi][3], d1, u[5]);       \
                fma2(acc[oi][0], d2, om[2]); fma2(acc[oi][1], d2, om[3]);      \
                fma2(acc[oi][2], d2, om[4]); fma2(acc[oi][3], d2, om[5]);      \
            } while(0)
            DOO1(0, w0.x, w1.x, w2.x);
            DOO1(1, w0.y, w1.y, w2.y);
            #undef DOO1
        }

        if (sp){
            // t=128 at window col 12 (local col 36); tap t+D is zero tail
            const float tm = (D == 4) ? lo2(u[4]) : (D == 2 ? lo2(u[5]) : hi2(u[5]));
            const float tz = lo2(u[6]);
            accx[0] = fmaf(w0.x, tm, fmaf(w1.x, tz, accx[0]));
            accx[1] = fmaf(w0.y, tm, fmaf(w1.y, tz, accx[1]));
        }

        hb += RS*4;
        wb += 384;
    }

    // ---- complete 128-channel sums: butterfly over the ch lane bit ----
    float res[2][8];
    #pragma unroll
    for (int oi = 0; oi < 2; oi++)
        #pragma unroll
        for (int p = 0; p < 4; p++){
            float a, b; unpk2(acc[oi][p], a, b);
            a += __shfl_xor_sync(0xffffffffu, a, 8);
            b += __shfl_xor_sync(0xffffffffu, b, 8);
            res[oi][2*p] = a; res[oi][2*p+1] = b;
        }
    accx[0] += __shfl_xor_sync(0xffffffffu, accx[0], 8);
    accx[1] += __shfl_xor_sync(0xffffffffu, accx[1], 8);

    CLUSTER_SYNC();   // (A) all reads of h complete cluster-wide

    // ---- epilogue: bias + relu + residual; update own cols + peer halos ----
    if (ch == 0){
        #pragma unroll
        for (int oi = 0; oi < 2; oi++){
            const int   o      = og*2 + oi;
            const int   rowoff = o*RS + ((o >= 64) ? 16 : 0);
            const float bias   = cb[o];
            float* own = hs + rowoff + 4 + tt*8;
            float hn[8];
            #pragma unroll
            for (int p = 0; p < 8; p++)
                hn[p] = fmaxf(res[oi][p] + bias, 0.f) + own[p];
            *(float4*)own       = make_float4(hn[0], hn[1], hn[2], hn[3]);
            *(float4*)(own + 4) = make_float4(hn[4], hn[5], hn[6], hn[7]);
            if (tt == 0 && tg > 0){          // my first 4 cols -> left peer's R-halo [36,40)
                st_cl_u64(lP + (uint32_t)(rowoff + 36)*4u, pk2(hn[0], hn[1]));
                st_cl_u64(lP + (uint32_t)(rowoff + 38)*4u, pk2(hn[2], hn[3]));
            }
            if (tt == 3 && tg < 3){          // my last 4 cols -> right peer's L-halo [0,4)
                st_cl_u64(rP + (uint32_t)(rowoff + 0)*4u, pk2(hn[4], hn[5]));
                st_cl_u64(rP + (uint32_t)(rowoff + 2)*4u, pk2(hn[6], hn[7]));
            }
            if (sp){                         // t=128 (local col 36), no consumer outside
                float v = fmaxf(accx[oi] + bias, 0.f) + hs[rowoff + 36];
                hs[rowoff + 36] = v;
            }
        }
    }

    CLUSTER_SYNC();   // (B) all h_new writes (local + DSMEM halos) visible
}

__global__ void __cluster_dims__(4, 1, 1) __launch_bounds__(NTHREADS, 1)
vgt_kernel(const int* __restrict__ x, const float* __restrict__ emb_w,
           const float* __restrict__ red_w, const float* __restrict__ red_b,
           const float* __restrict__ conv_w, const float* __restrict__ conv_b,
           const float* __restrict__ out_w, const float* __restrict__ out_b,
           float* __restrict__ out)
{
    extern __shared__ __align__(16) float sm[];
    float* ws = sm;                    // 49168 floats (padded weights)
    float* hs = ws + WS_FLOATS;        // 5648
    float* cb = hs + HS_FLOATS;        // 128
    float* m1 = cb + 128;              // 1280
    float* m2 = m1 + 1280;             // 1280

    const int tid = threadIdx.x;
    const int b   = blockIdx.x >> 2;
    const int tg  = blockIdx.x & 3;    // time-window group: owns t in [tg*32, tg*32+32) (+128 for tg3)

    const uint32_t hs_sh = (uint32_t)__cvta_generic_to_shared(hs);
    const uint32_t lP = (tg > 0) ? mapa32(hs_sh, (uint32_t)(tg - 1)) : 0u;
    const uint32_t rP = (tg < 3) ? mapa32(hs_sh, (uint32_t)(tg + 1)) : 0u;

    // ---- prologue: weights (padded), bias, reducer tables, h0 ----
    for (int idx = tid; idx < NH*3*NH; idx += NTHREADS){
        int o  = idx & 127;
        int ck = idx >> 7;          // = c*3 + k
        int k  = ck % 3;
        int c  = ck / 3;
        ws[idx + ((c >= 64) ? 16 : 0)] = conv_w[(o*NH + c)*3 + k];
    }
    if (tid < 128) cb[tid] = conv_b[tid];

    for (int idx = tid; idx < 10*NH; idx += NTHREADS){
        int v = idx >> 7;
        int o = idx & 127;
        const float* rw = red_w + o*(2*NH);
        const float* ew = emb_w + v*NH;
        float s1 = 0.f, s2 = 0.f;
        for (int c = 0; c < NH; c++){
            float e = ew[c];
            s1 = fmaf(rw[c],      e, s1);
            s2 = fmaf(rw[NH + c], e, s2);
        }
        m1[idx] = s1;
        m2[idx] = s2;
    }
    for (int idx = tid; idx < HS_FLOATS; idx += NTHREADS) hs[idx] = 0.f;
    __syncthreads();

    // h0 = relu(M1[x[t]] + M2[x[t+128]] + red_b) for local cols [0,40) (incl. halos);
    // t=128 initial value is the zero pad (stays 0).
    {
        const int* xb = x + b*256;
        for (int idx = tid; idx < NH*40; idx += NTHREADS){
            int o  = idx / 40;
            int ci = idx - o*40;
            int t  = tg*32 - 4 + ci;
            if (t >= 0 && t < 128){
                int v1 = xb[t];
                int v2 = xb[t + 128];
                float val = m1[v1*NH + o] + m2[v2*NH + o] + red_b[o];
                hs[o*RS + ((o >= 64) ? 16 : 0) + ci] = fmaxf(val, 0.f);
            }
        }
    }
    __syncthreads();
    CLUSTER_SYNC();

    // ---- 131 residual conv iterations, h fully smem-resident ----
    #pragma unroll 1
    for (int i = 0; i < 4; i++)  conv_iter<1>(hs, ws, cb, lP, rP, tg);
    #pragma unroll 1
    for (int i = 0; i < 4; i++)  conv_iter<2>(hs, ws, cb, lP, rP, tg);
    #pragma unroll 1
    for (int i = 0; i < NITER - 8; i++) conv_iter<4>(hs, ws, cb, lP, rP, tg);

    // ---- output head: out[b,t,o] = out_w . h[:,t] + out_b, own window ----
    {
        const int tcnt = (tg == 3) ? 33 : 32;
        for (int idx = tid; idx < tcnt*10; idx += NTHREADS){
            int tl = idx / 10;
            int o  = idx % 10;
            int t  = tg*32 + tl;
            int col = 4 + tl;
            const float* wrow = out_w + o*NH;
            float s = out_b[o];
            #pragma unroll 8
            for (int c = 0; c < NH; c++)
                s = fmaf(__ldg(wrow + c), hs[c*RS + ((c >= 64) ? 16 : 0) + col], s);
            out[(b*129 + t)*10 + o] = s;
        }
    }
}

extern "C" void kernel_launch(void* const* d_in, const int* in_sizes, int n_in,
                              void* d_out, int out_size)
{
    (void)in_sizes; (void)n_in; (void)out_size;
    const int*   x      = (const int*)  d_in[0];
    const float* emb_w  = (const float*)d_in[1];
    const float* red_w  = (const float*)d_in[2];
    const float* red_b  = (const float*)d_in[3];
    const float* conv_w = (const float*)d_in[4];
    const float* conv_b = (const float*)d_in[5];
    const float* out_w  = (const float*)d_in[6];
    const float* out_b  = (const float*)d_in[7];
    float* out = (float*)d_out;

    const size_t smem = (size_t)(WS_FLOATS + HS_FLOATS + 128 + 2*1280) * sizeof(float); // 230016 B
    cudaFuncSetAttribute(vgt_kernel, cudaFuncAttributeMaxDynamicSharedMemorySize, (int)smem);
    vgt_kernel<<<NB*4, NTHREADS, smem>>>(x, emb_w, red_w, red_b,
                                         conv_w, conv_b, out_w, out_b, out);
}